// round 11
// baseline (speedup 1.0000x reference)
#include <cuda_runtime.h>
#include <cuda_bf16.h>
#include <math_constants.h>

// Shapes fixed by the problem
#define BB 16
#define NP 8192
#define NG 128
#define NC 80
#define TPB 256
#define PREDS_PER_BLK 128          // 2 preds/thread over a QUARTER of the GTs
#define BPB (NP / PREDS_PER_BLK)   // 64 blocks per batch
#define NBLK (BB * BPB)            // 1024 blocks total

// Per-block partials: [sum_ciou_w, sum_ce_w, n_match, penalty, sum_bce_w, n_valid]
__device__ float    g_partials[NBLK * 8];
__device__ unsigned g_count;       // zero-init; reset by last block each launch

__global__ __launch_bounds__(TPB, 4)
void yolo_fused(const float4* __restrict__ y_hat,   // (B,NP,4) xywh
                const float4* __restrict__ y_gt,    // (B,NG,4) xywh
                const float*  __restrict__ obj,     // (B,NP)
                const float4* __restrict__ cls_pred,// (B,NP,NC)
                const int*    __restrict__ cls_tgt, // (B,NG)
                const int*    __restrict__ min_score,
                float* __restrict__ out)
{
    __shared__ float4   s_g[NG];     // gt xyxy
    __shared__ float    s_ga[NG];    // gt area
    __shared__ float    s_gw[NG];    // small-obj weight
    __shared__ int      s_gt[NG];    // gt class
    __shared__ int      s_key[4][PREDS_PER_BLK];  // [gt-quarter][pred slot]
    __shared__ float    s_red[8][6];
    __shared__ unsigned s_old;

    const int b    = blockIdx.x / BPB;
    const int base = b * NP + (blockIdx.x % BPB) * PREDS_PER_BLK;
    const int t    = threadIdx.x;
    const int tq   = t & 63;         // pred-slot group (handles 2 preds)
    const int h    = t >> 6;         // gt quarter (0..3)

    if (t < NG) {
        float4 g = y_gt[b * NG + t];
        float x1 = g.x - g.z * 0.5f, y1 = g.y - g.w * 0.5f;
        float x2 = g.x + g.z * 0.5f, y2 = g.y + g.w * 0.5f;
        s_g[t]  = make_float4(x1, y1, x2, y2);
        s_ga[t] = (x2 - x1) * (y2 - y1);
        s_gw[t] = (g.z < 0.05f || g.w < 0.05f) ? 2.0f : 1.0f;
        s_gt[t] = cls_tgt[b * NG + t];
    }
    __syncthreads();

    // ── Phase 1: each thread scans 2 preds × 32 GTs (one quarter) ──────
    // Monotone key: argmax iou == argmax inter/(area_p+area_g) since
    // x/(S-x) is increasing in x/S. Single clamp: inter' = max(iw,0)*ih
    // is <=0 for any non-overlap; SIGNED compare ranks those below every
    // positive key. Low 7 bits carry (127-g): first-occurrence tie-break
    // (g is the GLOBAL gt index, unique across quarters).
    {
        const int pA = base + tq, pB = base + tq + 64;
        float4 ha = y_hat[pA], hb = y_hat[pB];
        const float ax1 = ha.x - ha.z * 0.5f, ay1 = ha.y - ha.w * 0.5f;
        const float ax2 = ha.x + ha.z * 0.5f, ay2 = ha.y + ha.w * 0.5f;
        const float paA = (ax2 - ax1) * (ay2 - ay1);
        const float bx1 = hb.x - hb.z * 0.5f, by1 = hb.y - hb.w * 0.5f;
        const float bx2 = hb.x + hb.z * 0.5f, by2 = hb.y + hb.w * 0.5f;
        const float paB = (bx2 - bx1) * (by2 - by1);

        int bestA = (int)0x80000000, bestB = (int)0x80000000;
        const int g0 = h * 32;
        #pragma unroll 8
        for (int gi = 0; gi < 32; ++gi) {
            const int g = g0 + gi;
            float4 gb = s_g[g];
            float ga = s_ga[g];
            int tie = 127 - g;
            {   // pred A
                float iw = fminf(ax2, gb.z) - fmaxf(ax1, gb.x);
                float ih = fminf(ay2, gb.w) - fmaxf(ay1, gb.y);
                float inter = fmaxf(iw, 0.0f) * ih;        // <=0 if no overlap
                float r = __fdividef(inter, paA + ga);
                int key = (__float_as_int(r) & 0xFFFFFF80) | tie;
                bestA = bestA > key ? bestA : key;
            }
            {   // pred B
                float iw = fminf(bx2, gb.z) - fmaxf(bx1, gb.x);
                float ih = fminf(by2, gb.w) - fmaxf(by1, gb.y);
                float inter = fmaxf(iw, 0.0f) * ih;
                float r = __fdividef(inter, paB + ga);
                int key = (__float_as_int(r) & 0xFFFFFF80) | tie;
                bestB = bestB > key ? bestB : key;
            }
        }
        s_key[h][tq]      = bestA;
        s_key[h][tq + 64] = bestB;
    }
    __syncthreads();

    // ── Phase 2: threads 0..127 each handle pred base+t ─────────────────
    float acc0 = 0.f, acc1 = 0.f, acc2 = 0.f, acc3 = 0.f, acc4 = 0.f, acc5 = 0.f;
    if (t < PREDS_PER_BLK) {
        const int k0 = s_key[0][t], k1 = s_key[1][t];
        const int k2 = s_key[2][t], k3 = s_key[3][t];
        int best = k0 > k1 ? k0 : k1;
        best = best > k2 ? best : k2;
        best = best > k3 ? best : k3;
        const int gbest = 127 - (best & 127);

        const int p = base + t;
        float4 pb4 = y_hat[p];                     // L1/L2 hit
        const float px1 = pb4.x - pb4.z * 0.5f, py1 = pb4.y - pb4.w * 0.5f;
        const float px2 = pb4.x + pb4.z * 0.5f, py2 = pb4.y + pb4.w * 0.5f;
        const float pa  = (px2 - px1) * (py2 - py1);

        const float s   = obj[p];
        const float thr = (float)min_score[0];
        const bool  valid = s > thr;

        const float4 gb = s_g[gbest];
        const float  ga = s_ga[gbest];

        // Exact max_iou at winning index (reference iou_mat: no eps)
        float iw = fmaxf(fminf(px2, gb.z) - fmaxf(px1, gb.x), 0.0f);
        float ih = fmaxf(fminf(py2, gb.w) - fmaxf(py1, gb.y), 0.0f);
        float inter = iw * ih;
        float max_iou = inter / (pa + ga - inter);
        const bool matched = valid && (max_iou > 0.5f);

        if (valid) {
            acc5 = 1.0f;                                       // n_valid
            // valid => s > 0, so exp(-s) in (0,1): log(1+x) well-conditioned
            const float lbl = matched ? 1.0f : 0.0f;
            float bce = s - s * lbl + __logf(1.0f + __expf(-s));
            acc4 = (matched && s < 0.5f) ? 2.0f * bce : bce;   // sum_bce_w

            if (matched) {
                acc2 = 1.0f;                                   // n_match
                const float eps = 1e-7f;
                const float ws = s_gw[gbest];

                // CIoU (with eps, per reference)
                float uni_e = pa + ga - inter + eps;
                float iou   = inter / uni_e;
                float cw = fmaxf(px2, gb.z) - fminf(px1, gb.x);
                float ch = fmaxf(py2, gb.w) - fminf(py1, gb.y);
                float c2 = cw * cw + ch * ch + eps;
                float dx = (px1 + px2) * 0.5f - (gb.x + gb.z) * 0.5f;
                float dy = (py1 + py2) * 0.5f - (gb.y + gb.w) * 0.5f;
                float d2 = dx * dx + dy * dy;
                float w1 = px2 - px1, h1f = py2 - py1;
                float w2 = gb.z - gb.x, h2 = gb.w - gb.y;
                float dat = atanf(w1 / (h1f + eps)) - atanf(w2 / (h2 + eps));
                float v = (4.0f / (CUDART_PI_F * CUDART_PI_F)) * dat * dat;
                float alpha = v / (1.0f - iou + v + eps);
                float ciou = iou - (d2 / c2 + alpha * v);
                acc0 = (1.0f - ciou) * ws;                     // sum_ciou_w

                // Single-pass CE (logits ~N(0,1): exp safe without max-shift)
                const float4* row = cls_pred + (size_t)p * (NC / 4);
                float se = 0.0f;
                #pragma unroll
                for (int i = 0; i < NC / 4; ++i) {
                    float4 v4 = row[i];
                    se += __expf(v4.x) + __expf(v4.y) +
                          __expf(v4.z) + __expf(v4.w);
                }
                float lse = __logf(se);
                float xt  = ((const float*)row)[s_gt[gbest]];
                acc1 = (lse - xt) * ws;                        // sum_ce_w
            } else {
                acc3 = 0.1f * s;                               // penalty
            }
        }
    }

    // Deterministic block reduction (8 warps; warps 4-7 contribute zeros)
    const int lane = t & 31, warp = t >> 5;
    float accs[6] = {acc0, acc1, acc2, acc3, acc4, acc5};
    #pragma unroll
    for (int k = 0; k < 6; ++k) {
        float x = accs[k];
        #pragma unroll
        for (int o = 16; o; o >>= 1) x += __shfl_xor_sync(0xFFFFFFFFu, x, o);
        if (lane == 0) s_red[warp][k] = x;
    }
    __syncthreads();
    if (t == 0) {
        #pragma unroll
        for (int k = 0; k < 6; ++k)
            g_partials[blockIdx.x * 8 + k] =
                s_red[0][k] + s_red[1][k] + s_red[2][k] + s_red[3][k];
        __threadfence();
        s_old = atomicAdd(&g_count, 1u);
    }
    __syncthreads();

    // Last block: final deterministic reduction
    if (s_old == NBLK - 1) {
        __threadfence();
        __shared__ float s_loss[BB], s_vb[BB];
        if (t < BB) {
            float a0 = 0, a1 = 0, a2 = 0, a3 = 0, a4 = 0, a5 = 0;
            #pragma unroll 8
            for (int j = 0; j < BPB; ++j) {
                const float* qp = g_partials + (t * BPB + j) * 8;
                a0 += qp[0]; a1 += qp[1]; a2 += qp[2];
                a3 += qp[3]; a4 += qp[4]; a5 += qp[5];
            }
            float loc = (a2 > 0.f) ? a0 / a2 : 0.0f;
            float cls = (a2 > 0.f) ? a1 / a2 : 0.0f;
            float ob  = (a5 > 0.f) ? a4 / a5 : 0.0f;
            s_loss[t] = 5.0f * loc + ob + a3 + cls;
            s_vb[t]   = (a5 > 0.f) ? 1.0f : 0.0f;
        }
        __syncthreads();
        if (t == 0) {
            float sum = 0.f, cnt = 0.f;
            #pragma unroll
            for (int i = 0; i < BB; ++i) { sum += s_vb[i] * s_loss[i]; cnt += s_vb[i]; }
            out[0] = sum / fmaxf(cnt, 1.0f);
            g_count = 0u;   // reset for next graph replay
        }
    }
}

extern "C" void kernel_launch(void* const* d_in, const int* in_sizes, int n_in,
                              void* d_out, int out_size)
{
    const float4* y_hat    = (const float4*)d_in[0];
    const float4* y_gt     = (const float4*)d_in[1];
    const float*  obj      = (const float*) d_in[2];
    const float4* cls_pred = (const float4*)d_in[3];
    const int*    cls_tgt  = (const int*)   d_in[4];
    const int*    min_sc   = (const int*)   d_in[5];
    float* out = (float*)d_out;

    yolo_fused<<<NBLK, TPB>>>(y_hat, y_gt, obj, cls_pred, cls_tgt, min_sc, out);
}

// round 13
// speedup vs baseline: 1.3232x; 1.3232x over previous
#include <cuda_runtime.h>
#include <cuda_bf16.h>
#include <math_constants.h>

// Shapes fixed by the problem
#define BB 16
#define NP 8192
#define NG 128
#define NC 80
#define TPB 256
#define PREDS_PER_BLK 256
#define BPB (NP / PREDS_PER_BLK)   // 32 blocks per batch
#define NBLK (BB * BPB)            // 512 blocks total

// Per-block partials: [sum_ciou_w, sum_ce_w, n_match, penalty, sum_bce_w, n_valid]
__device__ float    g_partials[NBLK * 8];
__device__ unsigned g_count;       // zero-init; reset by last block each launch

__global__ __launch_bounds__(TPB, 4)
void yolo_fused(const float4* __restrict__ y_hat,   // (B,NP,4) xywh
                const float4* __restrict__ y_gt,    // (B,NG,4) xywh
                const float*  __restrict__ obj,     // (B,NP)
                const float4* __restrict__ cls_pred,// (B,NP,NC)
                const int*    __restrict__ cls_tgt, // (B,NG)
                const int*    __restrict__ min_score,
                float* __restrict__ out)
{
    __shared__ float4   s_g[NG];     // gt xyxy
    __shared__ float    s_ga[NG];    // gt area
    __shared__ float    s_gw[NG];    // small-obj weight
    __shared__ int      s_gt[NG];    // gt class
    __shared__ float4   s_cb[PREDS_PER_BLK];      // compacted pred xyxy
    __shared__ float    s_cpa[PREDS_PER_BLK];     // compacted pred area
    __shared__ int      s_cidx[PREDS_PER_BLK];    // pred slot -> compact idx
    __shared__ int      s_key[2][PREDS_PER_BLK];  // [gt-half][compact idx]
    __shared__ int      s_woff[9];
    __shared__ float    s_red[8][6];
    __shared__ unsigned s_old;

    const int b    = blockIdx.x / BPB;
    const int base = b * NP + (blockIdx.x % BPB) * PREDS_PER_BLK;
    const int t    = threadIdx.x;
    const int lane = t & 31, warp = t >> 5;

    const float thr = (float)min_score[0];

    if (t < NG) {
        float4 g = y_gt[b * NG + t];
        float x1 = g.x - g.z * 0.5f, y1 = g.y - g.w * 0.5f;
        float x2 = g.x + g.z * 0.5f, y2 = g.y + g.w * 0.5f;
        s_g[t]  = make_float4(x1, y1, x2, y2);
        s_ga[t] = (x2 - x1) * (y2 - y1);
        s_gw[t] = (g.z < 0.05f || g.w < 0.05f) ? 2.0f : 1.0f;
        s_gt[t] = cls_tgt[b * NG + t];
    }

    // ── Phase 0: compact valid preds (invalid preds contribute NOTHING,
    //    their match_idx is never used -> skip their IoU scan entirely) ──
    const int   p   = base + t;
    const float s   = obj[p];
    const bool  valid = s > thr;
    {
        unsigned m = __ballot_sync(0xFFFFFFFFu, valid);
        int lanepref = __popc(m & ((1u << lane) - 1u));
        if (lane == 0) s_woff[warp] = __popc(m);   // counts first
        __syncthreads();
        if (t == 0) {
            int o = 0;
            #pragma unroll
            for (int w = 0; w < 8; ++w) { int c = s_woff[w]; s_woff[w] = o; o += c; }
            s_woff[8] = o;
        }
        __syncthreads();
        if (valid) {
            float4 pb4 = y_hat[p];
            float x1 = pb4.x - pb4.z * 0.5f, y1 = pb4.y - pb4.w * 0.5f;
            float x2 = pb4.x + pb4.z * 0.5f, y2 = pb4.y + pb4.w * 0.5f;
            int c = s_woff[warp] + lanepref;
            s_cb[c]   = make_float4(x1, y1, x2, y2);
            s_cpa[c]  = (x2 - x1) * (y2 - y1);
            s_cidx[t] = c;
        }
    }
    __syncthreads();

    const int nv = s_woff[8];

    // ── Phase 1: scan only VALID preds: task = 2 compacted preds × 64 GTs.
    // tasks = 2*ceil(nv/2) <= 256, one per thread. Inner loop identical to
    // the proven 14-instr/pair core (signed key, global-g tie bits).
    {
        const int npair = (nv + 1) >> 1;
        const int tau = t;
        if (tau < 2 * npair) {
            const int pp = tau >> 1;
            const int hh = tau & 1;
            const int cA = 2 * pp;
            const int cB = (cA + 1 < nv) ? cA + 1 : cA;   // odd nv: dup, same key
            float4 ba = s_cb[cA]; const float paA = s_cpa[cA];
            float4 bb = s_cb[cB]; const float paB = s_cpa[cB];
            const float ax1 = ba.x, ay1 = ba.y, ax2 = ba.z, ay2 = ba.w;
            const float bx1 = bb.x, by1 = bb.y, bx2 = bb.z, by2 = bb.w;

            int bestA = (int)0x80000000, bestB = (int)0x80000000;
            const int g0 = hh * 64;
            #pragma unroll 8
            for (int gi = 0; gi < 64; ++gi) {
                const int g = g0 + gi;
                float4 gb = s_g[g];
                float ga = s_ga[g];
                int tie = 127 - g;
                {   // pred A
                    float iw = fminf(ax2, gb.z) - fmaxf(ax1, gb.x);
                    float ih = fminf(ay2, gb.w) - fmaxf(ay1, gb.y);
                    float inter = fmaxf(iw, 0.0f) * ih;    // <=0 if no overlap
                    float r = __fdividef(inter, paA + ga);
                    int key = (__float_as_int(r) & 0xFFFFFF80) | tie;
                    bestA = bestA > key ? bestA : key;
                }
                {   // pred B
                    float iw = fminf(bx2, gb.z) - fmaxf(bx1, gb.x);
                    float ih = fminf(by2, gb.w) - fmaxf(by1, gb.y);
                    float inter = fmaxf(iw, 0.0f) * ih;
                    float r = __fdividef(inter, paB + ga);
                    int key = (__float_as_int(r) & 0xFFFFFF80) | tie;
                    bestB = bestB > key ? bestB : key;
                }
            }
            s_key[hh][cA] = bestA;
            s_key[hh][cB] = bestB;   // cB==cA on odd tail: identical value
        }
    }
    __syncthreads();

    // ── Phase 2: thread t handles pred base+t (valid preds only) ────────
    float acc0 = 0.f, acc1 = 0.f, acc2 = 0.f, acc3 = 0.f, acc4 = 0.f, acc5 = 0.f;
    if (valid) {
        const int c  = s_cidx[t];
        const int k0 = s_key[0][c], k1 = s_key[1][c];
        const int best = k0 > k1 ? k0 : k1;
        const int gbest = 127 - (best & 127);

        const float4 pb4 = s_cb[c];
        const float px1 = pb4.x, py1 = pb4.y, px2 = pb4.z, py2 = pb4.w;
        const float pa  = s_cpa[c];

        const float4 gb = s_g[gbest];
        const float  ga = s_ga[gbest];

        // Exact max_iou at winning index (reference iou_mat: no eps)
        float iw = fmaxf(fminf(px2, gb.z) - fmaxf(px1, gb.x), 0.0f);
        float ih = fmaxf(fminf(py2, gb.w) - fmaxf(py1, gb.y), 0.0f);
        float inter = iw * ih;
        float max_iou = inter / (pa + ga - inter);
        const bool matched = max_iou > 0.5f;

        acc5 = 1.0f;                                       // n_valid
        // valid => s > 0, so exp(-s) in (0,1): log(1+x) well-conditioned
        const float lbl = matched ? 1.0f : 0.0f;
        float bce = s - s * lbl + __logf(1.0f + __expf(-s));
        acc4 = (matched && s < 0.5f) ? 2.0f * bce : bce;   // sum_bce_w

        if (matched) {
            acc2 = 1.0f;                                   // n_match
            const float eps = 1e-7f;
            const float ws = s_gw[gbest];

            // CIoU (with eps, per reference)
            float uni_e = pa + ga - inter + eps;
            float iou   = inter / uni_e;
            float cw = fmaxf(px2, gb.z) - fminf(px1, gb.x);
            float ch = fmaxf(py2, gb.w) - fminf(py1, gb.y);
            float c2 = cw * cw + ch * ch + eps;
            float dx = (px1 + px2) * 0.5f - (gb.x + gb.z) * 0.5f;
            float dy = (py1 + py2) * 0.5f - (gb.y + gb.w) * 0.5f;
            float d2 = dx * dx + dy * dy;
            float w1 = px2 - px1, h1f = py2 - py1;
            float w2 = gb.z - gb.x, h2 = gb.w - gb.y;
            float dat = atanf(w1 / (h1f + eps)) - atanf(w2 / (h2 + eps));
            float v = (4.0f / (CUDART_PI_F * CUDART_PI_F)) * dat * dat;
            float alpha = v / (1.0f - iou + v + eps);
            float ciou = iou - (d2 / c2 + alpha * v);
            acc0 = (1.0f - ciou) * ws;                     // sum_ciou_w

            // Single-pass CE (logits ~N(0,1): exp safe without max-shift)
            const float4* row = cls_pred + (size_t)p * (NC / 4);
            float se = 0.0f;
            #pragma unroll
            for (int i = 0; i < NC / 4; ++i) {
                float4 v4 = row[i];
                se += __expf(v4.x) + __expf(v4.y) +
                      __expf(v4.z) + __expf(v4.w);
            }
            float lse = __logf(se);
            float xt  = ((const float*)row)[s_gt[gbest]];
            acc1 = (lse - xt) * ws;                        // sum_ce_w
        } else {
            acc3 = 0.1f * s;                               // penalty
        }
    }

    // Deterministic block reduction (8 warps)
    float accs[6] = {acc0, acc1, acc2, acc3, acc4, acc5};
    #pragma unroll
    for (int k = 0; k < 6; ++k) {
        float x = accs[k];
        #pragma unroll
        for (int o = 16; o; o >>= 1) x += __shfl_xor_sync(0xFFFFFFFFu, x, o);
        if (lane == 0) s_red[warp][k] = x;
    }
    __syncthreads();
    if (t == 0) {
        #pragma unroll
        for (int k = 0; k < 6; ++k) {
            float x = 0.0f;
            #pragma unroll
            for (int w = 0; w < 8; ++w) x += s_red[w][k];
            g_partials[blockIdx.x * 8 + k] = x;
        }
        __threadfence();
        s_old = atomicAdd(&g_count, 1u);
    }
    __syncthreads();

    // Last block: final deterministic reduction
    if (s_old == NBLK - 1) {
        __threadfence();
        __shared__ float s_loss[BB], s_vb[BB];
        if (t < BB) {
            float a0 = 0, a1 = 0, a2 = 0, a3 = 0, a4 = 0, a5 = 0;
            #pragma unroll 8
            for (int j = 0; j < BPB; ++j) {
                const float* qp = g_partials + (t * BPB + j) * 8;
                a0 += qp[0]; a1 += qp[1]; a2 += qp[2];
                a3 += qp[3]; a4 += qp[4]; a5 += qp[5];
            }
            float loc = (a2 > 0.f) ? a0 / a2 : 0.0f;
            float cls = (a2 > 0.f) ? a1 / a2 : 0.0f;
            float ob  = (a5 > 0.f) ? a4 / a5 : 0.0f;
            s_loss[t] = 5.0f * loc + ob + a3 + cls;
            s_vb[t]   = (a5 > 0.f) ? 1.0f : 0.0f;
        }
        __syncthreads();
        if (t == 0) {
            float sum = 0.f, cnt = 0.f;
            #pragma unroll
            for (int i = 0; i < BB; ++i) { sum += s_vb[i] * s_loss[i]; cnt += s_vb[i]; }
            out[0] = sum / fmaxf(cnt, 1.0f);
            g_count = 0u;   // reset for next graph replay
        }
    }
}

extern "C" void kernel_launch(void* const* d_in, const int* in_sizes, int n_in,
                              void* d_out, int out_size)
{
    const float4* y_hat    = (const float4*)d_in[0];
    const float4* y_gt     = (const float4*)d_in[1];
    const float*  obj      = (const float*) d_in[2];
    const float4* cls_pred = (const float4*)d_in[3];
    const int*    cls_tgt  = (const int*)   d_in[4];
    const int*    min_sc   = (const int*)   d_in[5];
    float* out = (float*)d_out;

    yolo_fused<<<NBLK, TPB>>>(y_hat, y_gt, obj, cls_pred, cls_tgt, min_sc, out);
}